// round 14
// baseline (speedup 1.0000x reference)
#include <cuda_runtime.h>
#include <cuda_bf16.h>
#include <cstdint>

#define BATCH 32
#define SEQ   577
#define HEADS 12
#define HDIM  64
#define CDIM  768
#define MROWS (BATCH*SEQ)
#define QKVN  2304

__device__ __nv_bfloat16 g_Qh[(size_t)BATCH*HEADS*SEQ*HDIM], g_Ql[(size_t)BATCH*HEADS*SEQ*HDIM];
__device__ __nv_bfloat16 g_Kh[(size_t)BATCH*HEADS*SEQ*HDIM], g_Kl[(size_t)BATCH*HEADS*SEQ*HDIM];
__device__ __nv_bfloat16 g_Vh[(size_t)BATCH*HEADS*SEQ*HDIM], g_Vl[(size_t)BATCH*HEADS*SEQ*HDIM];
__device__ __nv_bfloat16 g_xh[(size_t)MROWS*CDIM], g_xl[(size_t)MROWS*CDIM];
__device__ __nv_bfloat16 g_wqh[(size_t)QKVN*CDIM], g_wql[(size_t)QKVN*CDIM];
__device__ __nv_bfloat16 g_wph[(size_t)CDIM*CDIM], g_wpl[(size_t)CDIM*CDIM];
__device__ __nv_bfloat16 g_ah[(size_t)MROWS*CDIM], g_al[(size_t)MROWS*CDIM];

// ---------------- helpers ----------------
__device__ __forceinline__ void ldsm4(uint32_t* r, uint32_t addr) {
    asm volatile("ldmatrix.sync.aligned.m8n8.x4.shared.b16 {%0,%1,%2,%3}, [%4];"
        : "=r"(r[0]), "=r"(r[1]), "=r"(r[2]), "=r"(r[3]) : "r"(addr));
}
__device__ __forceinline__ void ldsm4t(uint32_t* r, uint32_t addr) {
    asm volatile("ldmatrix.sync.aligned.m8n8.x4.trans.shared.b16 {%0,%1,%2,%3}, [%4];"
        : "=r"(r[0]), "=r"(r[1]), "=r"(r[2]), "=r"(r[3]) : "r"(addr));
}
__device__ __forceinline__ void mma_bf16(float* c, const uint32_t* a, const uint32_t* b) {
    asm volatile("mma.sync.aligned.m16n8k16.row.col.f32.bf16.bf16.f32 "
        "{%0,%1,%2,%3}, {%4,%5,%6,%7}, {%8,%9}, {%0,%1,%2,%3};"
        : "+f"(c[0]), "+f"(c[1]), "+f"(c[2]), "+f"(c[3])
        : "r"(a[0]), "r"(a[1]), "r"(a[2]), "r"(a[3]), "r"(b[0]), "r"(b[1]));
}
__device__ __forceinline__ void split2(float a, float b, uint32_t& hi, uint32_t& lo) {
    __nv_bfloat16 ha = __float2bfloat16_rn(a);
    __nv_bfloat16 hb = __float2bfloat16_rn(b);
    __nv_bfloat162 h; h.x = ha; h.y = hb;
    hi = *(uint32_t*)&h;
    __nv_bfloat16 la = __float2bfloat16_rn(a - __bfloat162float(ha));
    __nv_bfloat16 lb = __float2bfloat16_rn(b - __bfloat162float(hb));
    __nv_bfloat162 l; l.x = la; l.y = lb;
    lo = *(uint32_t*)&l;
}
__device__ __forceinline__ void cpa16(uint32_t dst, const void* src, int sz) {
    asm volatile("cp.async.cg.shared.global [%0], [%1], 16, %2;" :: "r"(dst), "l"(src), "r"(sz));
}
__device__ __forceinline__ void cpa_commit() { asm volatile("cp.async.commit_group;"); }
__device__ __forceinline__ void cpa_wait1()  { asm volatile("cp.async.wait_group 1;"); }

// ---------------- fp32 -> bf16 hi/lo split kernels ----------------
__device__ __forceinline__ void cvt_body(const float* __restrict__ s,
                                         __nv_bfloat16* __restrict__ hi,
                                         __nv_bfloat16* __restrict__ lo) {
    size_t i = ((size_t)blockIdx.x * 256 + threadIdx.x) * 4;
    float4 v = *(const float4*)(s + i);
    uint32_t h0, l0, h1, l1;
    split2(v.x, v.y, h0, l0);
    split2(v.z, v.w, h1, l1);
    *(uint32_t*)(hi + i) = h0; *(uint32_t*)(hi + i + 2) = h1;
    *(uint32_t*)(lo + i) = l0; *(uint32_t*)(lo + i + 2) = l1;
}
__global__ __launch_bounds__(256) void cvt_x_kernel(const float* __restrict__ s)  { cvt_body(s, g_xh, g_xl); }
__global__ __launch_bounds__(256) void cvt_wq_kernel(const float* __restrict__ s) { cvt_body(s, g_wqh, g_wql); }
__global__ __launch_bounds__(256) void cvt_wp_kernel(const float* __restrict__ s) { cvt_body(s, g_wph, g_wpl); }

// ---------------- HMMA GEMM core: 256x128 tile, BK=32, 16 warps (64x32 each)
// 3-stage cp.async, ONE sync per k-tile. A (256 rows) and B (128 rows), each
// 128B rows [hi 64B | lo 64B], 16B chunks XOR-swizzled by (row&7).
#define OA 0
#define OB 32768
#define STAGE_BYTES 49152
#define GEMM_SMEM (3*STAGE_BYTES)
#define NKT 24

__device__ __forceinline__ void mma_core(const __nv_bfloat16* __restrict__ Ah,
                                         const __nv_bfloat16* __restrict__ Al,
                                         const __nv_bfloat16* __restrict__ Bh,
                                         const __nv_bfloat16* __restrict__ Bl,
                                         int mBase, int nBase, float acc[4][4][4]) {
    extern __shared__ char smc[];
    const uint32_t su = (uint32_t)__cvta_generic_to_shared(smc);
    const int tid = threadIdx.x;
    const int lane = tid & 31, w = tid >> 5;
    const int wm = w & 3, wn = w >> 2;
    // A loaders: 512 threads -> 256 rows x 2 chunk-pairs
    const int ar = tid >> 1, ac0 = (tid & 1) * 2;     // chunks ac0, ac0+1 of hi half
    const int aSz = ((mBase + ar) < MROWS) ? 16 : 0;
    const __nv_bfloat16* pAh = Ah + (size_t)(mBase + ar) * CDIM + ac0 * 8;
    const __nv_bfloat16* pAl = Al + (size_t)(mBase + ar) * CDIM + ac0 * 8;
    const uint32_t stA0 = (uint32_t)ar * 128 + (uint32_t)((ac0       ^ (ar & 7)) << 4);
    const uint32_t stA1 = (uint32_t)ar * 128 + (uint32_t)(((ac0 + 1) ^ (ar & 7)) << 4);
    // B loaders: 512 threads -> 128 rows x 4 chunks
    const int br = tid >> 2, bc = tid & 3;
    const __nv_bfloat16* pBh = Bh + (size_t)(nBase + br) * CDIM + bc * 8;
    const __nv_bfloat16* pBl = Bl + (size_t)(nBase + br) * CDIM + bc * 8;
    const uint32_t stB = (uint32_t)br * 128 + (uint32_t)((bc ^ (br & 7)) << 4);
    // ldsm addressing (warp tile 64x32)
    const uint32_t lsw  = (uint32_t)(lane & 7);
    const uint32_t aRow = (uint32_t)(wm * 64 + (lane & 15));
    const uint32_t aKh  = (uint32_t)(lane >> 4);
    const uint32_t bRow = (uint32_t)(wn * 32 + ((lane >> 4) << 3) + (lane & 7));
    const uint32_t bKh  = (uint32_t)((lane >> 3) & 1);

    auto issue = [&](int t, int slot) {
        const uint32_t sb = su + (uint32_t)slot * STAGE_BYTES;
        const int k0 = t * 32;
        cpa16(sb + OA + stA0,        pAh + k0,     aSz);
        cpa16(sb + OA + stA1,        pAh + k0 + 8, aSz);
        cpa16(sb + OA + (stA0 ^ 64), pAl + k0,     aSz);
        cpa16(sb + OA + (stA1 ^ 64), pAl + k0 + 8, aSz);
        cpa16(sb + OB + stB,         pBh + k0,     16);
        cpa16(sb + OB + (stB ^ 64),  pBl + k0,     16);
        cpa_commit();
    };

    issue(0, 0);
    issue(1, 1);

    int slotC = 0, slotW = 2;
    for (int t = 0; t < NKT; t++) {
        cpa_wait1();
        __syncthreads();
        if (t + 2 < NKT) issue(t + 2, slotW);
        else             cpa_commit();
        const uint32_t sb = su + (uint32_t)slotC * STAGE_BYTES;
        #pragma unroll
        for (int ks = 0; ks < 2; ks++) {
            const uint32_t aOffH = (((uint32_t)(2*ks) + aKh) ^ lsw) << 4;
            const uint32_t bOffH = (((uint32_t)(2*ks) + bKh) ^ lsw) << 4;
            uint32_t af[4][4], bhf[4][2], blf[4][2];
            #pragma unroll
            for (int i = 0; i < 4; i++)
                ldsm4(af[i], sb + OA + (aRow + i*16)*128 + aOffH);
            #pragma unroll
            for (int j2 = 0; j2 < 2; j2++) {
                uint32_t r[4];
                ldsm4(r, sb + OB + (bRow + j2*16)*128 + bOffH);
                bhf[2*j2][0]=r[0]; bhf[2*j2][1]=r[1]; bhf[2*j2+1][0]=r[2]; bhf[2*j2+1][1]=r[3];
                ldsm4(r, sb + OB + (bRow + j2*16)*128 + (bOffH ^ 64));
                blf[2*j2][0]=r[0]; blf[2*j2][1]=r[1]; blf[2*j2+1][0]=r[2]; blf[2*j2+1][1]=r[3];
            }
            #pragma unroll
            for (int i = 0; i < 4; i++)
                #pragma unroll
                for (int j = 0; j < 4; j++)
                    mma_bf16(acc[i][j], af[i], bhf[j]);
            #pragma unroll
            for (int i = 0; i < 4; i++)
                #pragma unroll
                for (int j = 0; j < 4; j++)
                    mma_bf16(acc[i][j], af[i], blf[j]);
            #pragma unroll
            for (int i = 0; i < 4; i++)
                ldsm4(af[i], sb + OA + (aRow + i*16)*128 + (aOffH ^ 64));
            #pragma unroll
            for (int i = 0; i < 4; i++)
                #pragma unroll
                for (int j = 0; j < 4; j++)
                    mma_bf16(acc[i][j], af[i], bhf[j]);
        }
        slotC = (slotC == 2) ? 0 : slotC + 1;
        slotW = (slotW == 2) ? 0 : slotW + 1;
    }
}

// qkv: epilogue emits bf16 hi/lo Q/K/V (Q pre-scaled by 1/8)
__global__ __launch_bounds__(512, 1) void qkv_mma_kernel() {
    const int mBase = blockIdx.y * 256, nBase = blockIdx.x * 128;
    float acc[4][4][4];
    #pragma unroll
    for (int i = 0; i < 4; i++)
        #pragma unroll
        for (int j = 0; j < 4; j++)
            #pragma unroll
            for (int c = 0; c < 4; c++) acc[i][j][c] = 0.f;
    mma_core(g_xh, g_xl, g_wqh, g_wql, mBase, nBase, acc);

    const int lane = threadIdx.x & 31, w = threadIdx.x >> 5;
    const int wm = w & 3, wn = w >> 2;
    const int part = nBase / CDIM;
    __nv_bfloat16* dsth = (part == 0) ? g_Qh : (part == 1) ? g_Kh : g_Vh;
    __nv_bfloat16* dstl = (part == 0) ? g_Ql : (part == 1) ? g_Kl : g_Vl;
    const float scale = (part == 0) ? 0.125f : 1.0f;
    const int nOff = nBase - part * CDIM;
    #pragma unroll
    for (int i = 0; i < 4; i++) {
        const int m0 = mBase + wm*64 + i*16 + (lane >> 2);
        #pragma unroll
        for (int j = 0; j < 4; j++) {
            const int ncol = nOff + wn*32 + j*8 + (lane & 3)*2;
            const int hd = ncol >> 6, d0 = ncol & 63;
            if (m0 < MROWS) {
                int b = m0 / SEQ, q = m0 - b * SEQ;
                size_t idx = ((size_t)(b*HEADS + hd)*SEQ + q)*HDIM + d0;
                uint32_t hi, lo;
                split2(acc[i][j][0]*scale, acc[i][j][1]*scale, hi, lo);
                *(uint32_t*)(dsth + idx) = hi; *(uint32_t*)(dstl + idx) = lo;
            }
            const int m1 = m0 + 8;
            if (m1 < MROWS) {
                int b = m1 / SEQ, q = m1 - b * SEQ;
                size_t idx = ((size_t)(b*HEADS + hd)*SEQ + q)*HDIM + d0;
                uint32_t hi, lo;
                split2(acc[i][j][2]*scale, acc[i][j][3]*scale, hi, lo);
                *(uint32_t*)(dsth + idx) = hi; *(uint32_t*)(dstl + idx) = lo;
            }
        }
    }
}

__global__ __launch_bounds__(512, 1) void proj_mma_kernel(float* __restrict__ out,
                                                          const float* __restrict__ bias) {
    const int mBase = blockIdx.y * 256, nBase = blockIdx.x * 128;
    float acc[4][4][4];
    #pragma unroll
    for (int i = 0; i < 4; i++)
        #pragma unroll
        for (int j = 0; j < 4; j++)
            #pragma unroll
            for (int c = 0; c < 4; c++) acc[i][j][c] = 0.f;
    mma_core(g_ah, g_al, g_wph, g_wpl, mBase, nBase, acc);

    const int lane = threadIdx.x & 31, w = threadIdx.x >> 5;
    const int wm = w & 3, wn = w >> 2;
    #pragma unroll
    for (int i = 0; i < 4; i++) {
        const int m0 = mBase + wm*64 + i*16 + (lane >> 2);
        #pragma unroll
        for (int j = 0; j < 4; j++) {
            const int ncol = nBase + wn*32 + j*8 + (lane & 3)*2;
            const float2 bv = *(const float2*)(bias + ncol);
            if (m0 < MROWS)
                *(float2*)(out + (size_t)m0*CDIM + ncol) =
                    make_float2(acc[i][j][0] + bv.x, acc[i][j][1] + bv.y);
            const int m1 = m0 + 8;
            if (m1 < MROWS)
                *(float2*)(out + (size_t)m1*CDIM + ncol) =
                    make_float2(acc[i][j][2] + bv.x, acc[i][j][3] + bv.y);
        }
    }
}

// ---------------- HMMA flash attention (unchanged from R8/R13) ----------------
#define AT_ROWB 144
#define AQH 0
#define AQL 18432
#define AKH 36864
#define AKL 46080
#define AVH 55296
#define AVL 64512
#define ATTN_SMEM 73728

__global__ __launch_bounds__(256, 2) void attn_kernel_fn() {
    extern __shared__ char smc[];
    const uint32_t su = (uint32_t)__cvta_generic_to_shared(smc);
    const int tid = threadIdx.x;
    const int lane = tid & 31, w = tid >> 5;
    const int b = blockIdx.z, h = blockIdx.y;
    const int q0 = blockIdx.x * 128;
    const size_t base = (size_t)(b*HEADS + h) * SEQ * HDIM;
    const uint4 z = make_uint4(0, 0, 0, 0);

    #pragma unroll
    for (int t = 0; t < 4; t++) {
        int idx = t*256 + tid;
        int r = idx >> 3, c8 = (idx & 7) * 8;
        uint4 vh = z, vl = z;
        if (q0 + r < SEQ) {
            size_t g = base + (size_t)(q0 + r)*HDIM + c8;
            vh = *(const uint4*)(g_Qh + g);
            vl = *(const uint4*)(g_Ql + g);
        }
        *(uint4*)(smc + AQH + r*AT_ROWB + c8*2) = vh;
        *(uint4*)(smc + AQL + r*AT_ROWB + c8*2) = vl;
    }

    const uint32_t aoff  = (uint32_t)((w*16 + (lane&7) + ((lane>>3)&1)*8) * AT_ROWB + ((lane>>4)&1)*16);
    const uint32_t boffK = (uint32_t)((((lane>>4)&1)*8 + (lane&7)) * AT_ROWB + ((lane>>3)&1)*16);
    const uint32_t boffV = (uint32_t)(((lane&7) + ((lane>>3)&1)*8) * AT_ROWB + ((lane>>4)&1)*16);

    float o[8][4];
    #pragma unroll
    for (int j = 0; j < 8; j++)
        #pragma unroll
        for (int c = 0; c < 4; c++) o[j][c] = 0.f;
    float mi0 = -1e30f, mi1 = -1e30f, li0 = 0.f, li1 = 0.f;

    for (int kt = 0; kt < 10; kt++) {
        const int c0 = kt * 64;
        const int nk = (SEQ - c0 < 64) ? (SEQ - c0) : 64;
        __syncthreads();
        #pragma unroll
        for (int t = 0; t < 2; t++) {
            int idx = t*256 + tid;
            int r = idx >> 3, c8 = (idx & 7) * 8;
            uint4 kh = z, kl = z, vh = z, vl = z;
            if (r < nk) {
                size_t g = base + (size_t)(c0 + r)*HDIM + c8;
                kh = *(const uint4*)(g_Kh + g); kl = *(const uint4*)(g_Kl + g);
                vh = *(const uint4*)(g_Vh + g); vl = *(const uint4*)(g_Vl + g);
            }
            uint32_t so = (uint32_t)(r*AT_ROWB + c8*2);
            *(uint4*)(smc + AKH + so) = kh; *(uint4*)(smc + AKL + so) = kl;
            *(uint4*)(smc + AVH + so) = vh; *(uint4*)(smc + AVL + so) = vl;
        }
        __syncthreads();

        float sc[8][4];
        #pragma unroll
        for (int j = 0; j < 8; j++)
            #pragma unroll
            for (int c = 0; c < 4; c++) sc[j][c] = 0.f;
        #pragma unroll
        for (int t = 0; t < 4; t++) {
            uint32_t kf[4][4], aq[4];
            #pragma unroll
            for (int j2 = 0; j2 < 4; j2++)
                ldsm4(kf[j2], su + AKH + boffK + (uint32_t)(j2*16*AT_ROWB) + t*32);
            ldsm4(aq, su + AQH + aoff + t*32);
            #pragma unroll
            for (int j2 = 0; j2 < 4; j2++) {
                mma_bf16(sc[2*j2],   aq, &kf[j2][0]);
                mma_bf16(sc[2*j2+1], aq, &kf[j2][2]);
            }
            ldsm4(aq, su + AQL + aoff + t*32);
            #pragma unroll
            for (int j2 = 0; j2 < 4; j2++) {
                mma_bf16(sc[2*j2],   aq, &kf[j2][0]);
                mma_bf16(sc[2*j2+1], aq, &kf[j2][2]);
            }
            #pragma unroll
            for (int j2 = 0; j2 < 4; j2++)
                ldsm4(kf[j2], su + AKL + boffK + (uint32_t)(j2*16*AT_ROWB) + t*32);
            ldsm4(aq, su + AQH + aoff + t*32);
            #pragma unroll
            for (int j2 = 0; j2 < 4; j2++) {
                mma_bf16(sc[2*j2],   aq, &kf[j2][0]);
                mma_bf16(sc[2*j2+1], aq, &kf[j2][2]);
            }
        }

        if (nk < 64) {
            #pragma unroll
            for (int j = 0; j < 8; j++) {
                int col = 8*j + (lane & 3)*2;
                if (col   >= nk) { sc[j][0] = -1e30f; sc[j][2] = -1e30f; }
                if (col+1 >= nk) { sc[j][1] = -1e30f; sc[j][3] = -1e30f; }
            }
        }

        float m0 = -1e30f, m1 = -1e30f;
        #pragma unroll
        for (int j = 0; j < 8; j++) {
            m0 = fmaxf(m0, fmaxf(sc[j][0], sc[j][1]));
            m1 = fmaxf(m1, fmaxf(sc[j][2], sc[j][3]));
        }
        m0 = fmaxf(m0, __shfl_xor_sync(0xffffffffu, m0, 1));
        m0 = fmaxf(m0, __shfl_xor_sync(0xffffffffu, m0, 2));
        m1 = fmaxf(m1, __shfl_xor_sync(0xffffffffu, m1, 1));
        m1 = fmaxf(m1, __shfl_xor_sync(0xffffffffu, m1, 2));
        float mn0 = fmaxf(mi0, m0), mn1 = fmaxf(mi1, m1);
        float cr0 = __expf(mi0 - mn0), cr1 = __expf(mi1 - mn1);
        float rs0 = 0.f, rs1 = 0.f;
        #pragma unroll
        for (int j = 0; j < 8; j++) {
            sc[j][0] = __expf(sc[j][0] - mn0); rs0 += sc[j][0];
            sc[j][1] = __expf(sc[j][1] - mn0); rs0 += sc[j][1];
            sc[j][2] = __expf(sc[j][2] - mn1); rs1 += sc[j][2];
            sc[j][3] = __expf(sc[j][3] - mn1); rs1 += sc[j][3];
        }
        rs0 += __shfl_xor_sync(0xffffffffu, rs0, 1);
        rs0 += __shfl_xor_sync(0xffffffffu, rs0, 2);
        rs1 += __shfl_xor_sync(0xffffffffu, rs1, 1);
        rs1 += __shfl_xor_sync(0xffffffffu, rs1, 2);
        li0 = li0*cr0 + rs0; li1 = li1*cr1 + rs1;
        mi0 = mn0; mi1 = mn1;
        #pragma unroll
        for (int j = 0; j < 8; j++) {
            o[j][0] *= cr0; o[j][1] *= cr0;
            o[j][2] *= cr1; o[j][3] *= cr1;
        }

        #pragma unroll
        for (int tk = 0; tk < 4; tk++) {
            uint32_t ah[4], al[4];
            split2(sc[2*tk][0],   sc[2*tk][1],   ah[0], al[0]);
            split2(sc[2*tk][2],   sc[2*tk][3],   ah[1], al[1]);
            split2(sc[2*tk+1][0], sc[2*tk+1][1], ah[2], al[2]);
            split2(sc[2*tk+1][2], sc[2*tk+1][3], ah[3], al[3]);
            #pragma unroll
            for (int j2 = 0; j2 < 4; j2++) {
                uint32_t vf[4];
                ldsm4t(vf, su + AVH + boffV + (uint32_t)(tk*16*AT_ROWB) + j2*32);
                mma_bf16(o[2*j2],   ah, &vf[0]);
                mma_bf16(o[2*j2+1], ah, &vf[2]);
                mma_bf16(o[2*j2],   al, &vf[0]);
                mma_bf16(o[2*j2+1], al, &vf[2]);
                ldsm4t(vf, su + AVL + boffV + (uint32_t)(tk*16*AT_ROWB) + j2*32);
                mma_bf16(o[2*j2],   ah, &vf[0]);
                mma_bf16(o[2*j2+1], ah, &vf[2]);
            }
        }
    }

    float inv0 = 1.f / li0, inv1 = 1.f / li1;
    const int r0 = q0 + w*16 + (lane >> 2), r1 = r0 + 8;
    #pragma unroll
    for (int j = 0; j < 8; j++) {
        const int col = h*HDIM + 8*j + (lane & 3)*2;
        if (r0 < SEQ) {
            uint32_t hi, lo;
            split2(o[j][0]*inv0, o[j][1]*inv0, hi, lo);
            size_t idx = ((size_t)b*SEQ + r0)*CDIM + col;
            *(uint32_t*)(g_ah + idx) = hi; *(uint32_t*)(g_al + idx) = lo;
        }
        if (r1 < SEQ) {
            uint32_t hi, lo;
            split2(o[j][2]*inv1, o[j][3]*inv1, hi, lo);
            size_t idx = ((size_t)b*SEQ + r1)*CDIM + col;
            *(uint32_t*)(g_ah + idx) = hi; *(uint32_t*)(g_al + idx) = lo;
        }
    }
}

extern "C" void kernel_launch(void* const* d_in, const int* in_sizes, int n_in,
                              void* d_out, int out_size) {
    const float* x     = (const float*)d_in[0];
    const float* Wqkv  = (const float*)d_in[1];
    const float* Wproj = (const float*)d_in[2];
    const float* bproj = (const float*)d_in[3];
    float* out = (float*)d_out;
    (void)in_sizes; (void)n_in; (void)out_size;

    cudaFuncSetAttribute(qkv_mma_kernel,  cudaFuncAttributeMaxDynamicSharedMemorySize, GEMM_SMEM);
    cudaFuncSetAttribute(proj_mma_kernel, cudaFuncAttributeMaxDynamicSharedMemorySize, GEMM_SMEM);
    cudaFuncSetAttribute(attn_kernel_fn,  cudaFuncAttributeMaxDynamicSharedMemorySize, ATTN_SMEM);

    cvt_x_kernel <<<13848, 256>>>(x);
    cvt_wq_kernel<<<1728,  256>>>(Wqkv);
    cvt_wp_kernel<<<576,   256>>>(Wproj);
    qkv_mma_kernel<<<dim3(18, 73), 512, GEMM_SMEM>>>();
    attn_kernel_fn<<<dim3(5, HEADS, BATCH), 256, ATTN_SMEM>>>();
    proj_mma_kernel<<<dim3(6, 73), 512, GEMM_SMEM>>>(out, bproj);
}

// round 15
// speedup vs baseline: 1.0110x; 1.0110x over previous
#include <cuda_runtime.h>
#include <cuda_bf16.h>
#include <cstdint>

#define BATCH 32
#define SEQ   577
#define HEADS 12
#define HDIM  64
#define CDIM  768
#define MROWS (BATCH*SEQ)
#define QKVN  2304

__device__ __nv_bfloat16 g_Qh[(size_t)BATCH*HEADS*SEQ*HDIM], g_Ql[(size_t)BATCH*HEADS*SEQ*HDIM];
__device__ __nv_bfloat16 g_Kh[(size_t)BATCH*HEADS*SEQ*HDIM], g_Kl[(size_t)BATCH*HEADS*SEQ*HDIM];
__device__ __nv_bfloat16 g_Vh[(size_t)BATCH*HEADS*SEQ*HDIM], g_Vl[(size_t)BATCH*HEADS*SEQ*HDIM];
__device__ __nv_bfloat16 g_xh[(size_t)MROWS*CDIM], g_xl[(size_t)MROWS*CDIM];
__device__ __nv_bfloat16 g_wqh[(size_t)QKVN*CDIM], g_wql[(size_t)QKVN*CDIM];
__device__ __nv_bfloat16 g_wph[(size_t)CDIM*CDIM], g_wpl[(size_t)CDIM*CDIM];
__device__ __nv_bfloat16 g_ah[(size_t)MROWS*CDIM], g_al[(size_t)MROWS*CDIM];

// ---------------- helpers ----------------
__device__ __forceinline__ void ldsm4(uint32_t* r, uint32_t addr) {
    asm volatile("ldmatrix.sync.aligned.m8n8.x4.shared.b16 {%0,%1,%2,%3}, [%4];"
        : "=r"(r[0]), "=r"(r[1]), "=r"(r[2]), "=r"(r[3]) : "r"(addr));
}
__device__ __forceinline__ void ldsm4t(uint32_t* r, uint32_t addr) {
    asm volatile("ldmatrix.sync.aligned.m8n8.x4.trans.shared.b16 {%0,%1,%2,%3}, [%4];"
        : "=r"(r[0]), "=r"(r[1]), "=r"(r[2]), "=r"(r[3]) : "r"(addr));
}
__device__ __forceinline__ void mma_bf16(float* c, const uint32_t* a, const uint32_t* b) {
    asm volatile("mma.sync.aligned.m16n8k16.row.col.f32.bf16.bf16.f32 "
        "{%0,%1,%2,%3}, {%4,%5,%6,%7}, {%8,%9}, {%0,%1,%2,%3};"
        : "+f"(c[0]), "+f"(c[1]), "+f"(c[2]), "+f"(c[3])
        : "r"(a[0]), "r"(a[1]), "r"(a[2]), "r"(a[3]), "r"(b[0]), "r"(b[1]));
}
__device__ __forceinline__ void split2(float a, float b, uint32_t& hi, uint32_t& lo) {
    __nv_bfloat16 ha = __float2bfloat16_rn(a);
    __nv_bfloat16 hb = __float2bfloat16_rn(b);
    __nv_bfloat162 h; h.x = ha; h.y = hb;
    hi = *(uint32_t*)&h;
    __nv_bfloat16 la = __float2bfloat16_rn(a - __bfloat162float(ha));
    __nv_bfloat16 lb = __float2bfloat16_rn(b - __bfloat162float(hb));
    __nv_bfloat162 l; l.x = la; l.y = lb;
    lo = *(uint32_t*)&l;
}
__device__ __forceinline__ void cpa16(uint32_t dst, const void* src, int sz) {
    asm volatile("cp.async.cg.shared.global [%0], [%1], 16, %2;" :: "r"(dst), "l"(src), "r"(sz));
}
__device__ __forceinline__ void cpa_commit() { asm volatile("cp.async.commit_group;"); }
__device__ __forceinline__ void cpa_wait1()  { asm volatile("cp.async.wait_group 1;"); }

// ---------------- fp32 -> bf16 hi/lo split kernels ----------------
__device__ __forceinline__ void cvt_body(const float* __restrict__ s,
                                         __nv_bfloat16* __restrict__ hi,
                                         __nv_bfloat16* __restrict__ lo) {
    size_t i = ((size_t)blockIdx.x * 256 + threadIdx.x) * 4;
    float4 v = *(const float4*)(s + i);
    uint32_t h0, l0, h1, l1;
    split2(v.x, v.y, h0, l0);
    split2(v.z, v.w, h1, l1);
    *(uint32_t*)(hi + i) = h0; *(uint32_t*)(hi + i + 2) = h1;
    *(uint32_t*)(lo + i) = l0; *(uint32_t*)(lo + i + 2) = l1;
}
__global__ __launch_bounds__(256) void cvt_x_kernel(const float* __restrict__ s)  { cvt_body(s, g_xh, g_xl); }
__global__ __launch_bounds__(256) void cvt_wq_kernel(const float* __restrict__ s) { cvt_body(s, g_wqh, g_wql); }
__global__ __launch_bounds__(256) void cvt_wp_kernel(const float* __restrict__ s) { cvt_body(s, g_wph, g_wpl); }

// ---------------- HMMA GEMM core: 128x128 tile, BK=64, 16 warps (32x32 each)
// 3-stage cp.async, ONE sync per k-tile (12 k-tiles). A and B: 256B rows
// [hi 128B | lo 128B], 16B chunks XOR-swizzled by (row&7) within each half.
#define OA 0
#define OB 32768
#define STAGE_BYTES 65536
#define GEMM_SMEM (3*STAGE_BYTES)
#define NKT 12

__device__ __forceinline__ void mma_core(const __nv_bfloat16* __restrict__ Ah,
                                         const __nv_bfloat16* __restrict__ Al,
                                         const __nv_bfloat16* __restrict__ Bh,
                                         const __nv_bfloat16* __restrict__ Bl,
                                         int mBase, int nBase, float acc[2][4][4]) {
    extern __shared__ char smc[];
    const uint32_t su = (uint32_t)__cvta_generic_to_shared(smc);
    const int tid = threadIdx.x;
    const int lane = tid & 31, w = tid >> 5;
    const int wm = w & 3, wn = w >> 2;
    // loaders: 512 threads; row = tid>>2 (0..127), chunk pair c0 = (tid&3)*2
    const int lrow = tid >> 2, c0 = (tid & 3) * 2;
    const int aSz = ((mBase + lrow) < MROWS) ? 16 : 0;
    const __nv_bfloat16* pAh = Ah + (size_t)(mBase + lrow) * CDIM + c0 * 8;
    const __nv_bfloat16* pAl = Al + (size_t)(mBase + lrow) * CDIM + c0 * 8;
    const __nv_bfloat16* pBh = Bh + (size_t)(nBase + lrow) * CDIM + c0 * 8;
    const __nv_bfloat16* pBl = Bl + (size_t)(nBase + lrow) * CDIM + c0 * 8;
    const uint32_t st0 = (uint32_t)lrow * 256 + (uint32_t)((c0       ^ (lrow & 7)) << 4);
    const uint32_t st1 = (uint32_t)lrow * 256 + (uint32_t)(((c0 + 1) ^ (lrow & 7)) << 4);
    // ldsm addressing (warp tile 32x32)
    const uint32_t lsw  = (uint32_t)(lane & 7);
    const uint32_t aRow = (uint32_t)(wm * 32 + (lane & 15));
    const uint32_t aKh  = (uint32_t)(lane >> 4);
    const uint32_t bRow = (uint32_t)(wn * 32 + ((lane >> 4) << 3) + (lane & 7));
    const uint32_t bKh  = (uint32_t)((lane >> 3) & 1);

    auto issue = [&](int t, int slot) {
        const uint32_t sb = su + (uint32_t)slot * STAGE_BYTES;
        const int k0 = t * 64;
        cpa16(sb + OA + st0,         pAh + k0,     aSz);
        cpa16(sb + OA + st1,         pAh + k0 + 8, aSz);
        cpa16(sb + OA + st0 + 128,   pAl + k0,     aSz);
        cpa16(sb + OA + st1 + 128,   pAl + k0 + 8, aSz);
        cpa16(sb + OB + st0,         pBh + k0,     16);
        cpa16(sb + OB + st1,         pBh + k0 + 8, 16);
        cpa16(sb + OB + st0 + 128,   pBl + k0,     16);
        cpa16(sb + OB + st1 + 128,   pBl + k0 + 8, 16);
        cpa_commit();
    };

    issue(0, 0);
    issue(1, 1);

    int slotC = 0, slotW = 2;
    for (int t = 0; t < NKT; t++) {
        cpa_wait1();
        __syncthreads();
        if (t + 2 < NKT) issue(t + 2, slotW);
        else             cpa_commit();
        const uint32_t sb = su + (uint32_t)slotC * STAGE_BYTES;
        #pragma unroll
        for (int ks = 0; ks < 4; ks++) {
            const uint32_t aOffH = (((uint32_t)(2*ks) + aKh) ^ lsw) << 4;
            const uint32_t bOffH = (((uint32_t)(2*ks) + bKh) ^ lsw) << 4;
            uint32_t af[2][4], bhf[4][2], blf[4][2];
            #pragma unroll
            for (int i = 0; i < 2; i++)
                ldsm4(af[i], sb + OA + (aRow + i*16)*256 + aOffH);
            #pragma unroll
            for (int j2 = 0; j2 < 2; j2++) {
                uint32_t r[4];
                ldsm4(r, sb + OB + (bRow + j2*16)*256 + bOffH);
                bhf[2*j2][0]=r[0]; bhf[2*j2][1]=r[1]; bhf[2*j2+1][0]=r[2]; bhf[2*j2+1][1]=r[3];
                ldsm4(r, sb + OB + (bRow + j2*16)*256 + bOffH + 128);
                blf[2*j2][0]=r[0]; blf[2*j2][1]=r[1]; blf[2*j2+1][0]=r[2]; blf[2*j2+1][1]=r[3];
            }
            #pragma unroll
            for (int i = 0; i < 2; i++)
                #pragma unroll
                for (int j = 0; j < 4; j++)
                    mma_bf16(acc[i][j], af[i], bhf[j]);
            #pragma unroll
            for (int i = 0; i < 2; i++)
                #pragma unroll
                for (int j = 0; j < 4; j++)
                    mma_bf16(acc[i][j], af[i], blf[j]);
            #pragma unroll
            for (int i = 0; i < 2; i++)
                ldsm4(af[i], sb + OA + (aRow + i*16)*256 + aOffH + 128);
            #pragma unroll
            for (int i = 0; i < 2; i++)
                #pragma unroll
                for (int j = 0; j < 4; j++)
                    mma_bf16(acc[i][j], af[i], bhf[j]);
        }
        slotC = (slotC == 2) ? 0 : slotC + 1;
        slotW = (slotW == 2) ? 0 : slotW + 1;
    }
}

// qkv: epilogue emits bf16 hi/lo Q/K/V (Q pre-scaled by 1/8)
__global__ __launch_bounds__(512, 1) void qkv_mma_kernel() {
    const int mBase = blockIdx.y * 128, nBase = blockIdx.x * 128;
    float acc[2][4][4];
    #pragma unroll
    for (int i = 0; i < 2; i++)
        #pragma unroll
        for (int j = 0; j < 4; j++)
            #pragma unroll
            for (int c = 0; c < 4; c++) acc[i][j][c] = 0.f;
    mma_core(g_xh, g_xl, g_wqh, g_wql, mBase, nBase, acc);

    const int lane = threadIdx.x & 31, w = threadIdx.x >> 5;
    const int wm = w & 3, wn = w >> 2;
    const int part = nBase / CDIM;
    __nv_bfloat16* dsth = (part == 0) ? g_Qh : (part == 1) ? g_Kh : g_Vh;
    __nv_bfloat16* dstl = (part == 0) ? g_Ql : (part == 1) ? g_Kl : g_Vl;
    const float scale = (part == 0) ? 0.125f : 1.0f;
    const int nOff = nBase - part * CDIM;
    #pragma unroll
    for (int i = 0; i < 2; i++) {
        const int m0 = mBase + wm*32 + i*16 + (lane >> 2);
        #pragma unroll
        for (int j = 0; j < 4; j++) {
            const int ncol = nOff + wn*32 + j*8 + (lane & 3)*2;
            const int hd = ncol >> 6, d0 = ncol & 63;
            if (m0 < MROWS) {
                int b = m0 / SEQ, q = m0 - b * SEQ;
                size_t idx = ((size_t)(b*HEADS + hd)*SEQ + q)*HDIM + d0;
                uint32_t hi, lo;
                split2(acc[i][j][0]*scale, acc[i][j][1]*scale, hi, lo);
                *(uint32_t*)(dsth + idx) = hi; *(uint32_t*)(dstl + idx) = lo;
            }
            const int m1 = m0 + 8;
            if (m1 < MROWS) {
                int b = m1 / SEQ, q = m1 - b * SEQ;
                size_t idx = ((size_t)(b*HEADS + hd)*SEQ + q)*HDIM + d0;
                uint32_t hi, lo;
                split2(acc[i][j][2]*scale, acc[i][j][3]*scale, hi, lo);
                *(uint32_t*)(dsth + idx) = hi; *(uint32_t*)(dstl + idx) = lo;
            }
        }
    }
}

__global__ __launch_bounds__(512, 1) void proj_mma_kernel(float* __restrict__ out,
                                                          const float* __restrict__ bias) {
    const int mBase = blockIdx.y * 128, nBase = blockIdx.x * 128;
    float acc[2][4][4];
    #pragma unroll
    for (int i = 0; i < 2; i++)
        #pragma unroll
        for (int j = 0; j < 4; j++)
            #pragma unroll
            for (int c = 0; c < 4; c++) acc[i][j][c] = 0.f;
    mma_core(g_ah, g_al, g_wph, g_wpl, mBase, nBase, acc);

    const int lane = threadIdx.x & 31, w = threadIdx.x >> 5;
    const int wm = w & 3, wn = w >> 2;
    #pragma unroll
    for (int i = 0; i < 2; i++) {
        const int m0 = mBase + wm*32 + i*16 + (lane >> 2);
        #pragma unroll
        for (int j = 0; j < 4; j++) {
            const int ncol = nBase + wn*32 + j*8 + (lane & 3)*2;
            const float2 bv = *(const float2*)(bias + ncol);
            if (m0 < MROWS)
                *(float2*)(out + (size_t)m0*CDIM + ncol) =
                    make_float2(acc[i][j][0] + bv.x, acc[i][j][1] + bv.y);
            const int m1 = m0 + 8;
            if (m1 < MROWS)
                *(float2*)(out + (size_t)m1*CDIM + ncol) =
                    make_float2(acc[i][j][2] + bv.x, acc[i][j][3] + bv.y);
        }
    }
}

// ---------------- HMMA flash attention (unchanged from R8/R13) ----------------
#define AT_ROWB 144
#define AQH 0
#define AQL 18432
#define AKH 36864
#define AKL 46080
#define AVH 55296
#define AVL 64512
#define ATTN_SMEM 73728

__global__ __launch_bounds__(256, 2) void attn_kernel_fn() {
    extern __shared__ char smc[];
    const uint32_t su = (uint32_t)__cvta_generic_to_shared(smc);
    const int tid = threadIdx.x;
    const int lane = tid & 31, w = tid >> 5;
    const int b = blockIdx.z, h = blockIdx.y;
    const int q0 = blockIdx.x * 128;
    const size_t base = (size_t)(b*HEADS + h) * SEQ * HDIM;
    const uint4 z = make_uint4(0, 0, 0, 0);

    #pragma unroll
    for (int t = 0; t < 4; t++) {
        int idx = t*256 + tid;
        int r = idx >> 3, c8 = (idx & 7) * 8;
        uint4 vh = z, vl = z;
        if (q0 + r < SEQ) {
            size_t g = base + (size_t)(q0 + r)*HDIM + c8;
            vh = *(const uint4*)(g_Qh + g);
            vl = *(const uint4*)(g_Ql + g);
        }
        *(uint4*)(smc + AQH + r*AT_ROWB + c8*2) = vh;
        *(uint4*)(smc + AQL + r*AT_ROWB + c8*2) = vl;
    }

    const uint32_t aoff  = (uint32_t)((w*16 + (lane&7) + ((lane>>3)&1)*8) * AT_ROWB + ((lane>>4)&1)*16);
    const uint32_t boffK = (uint32_t)((((lane>>4)&1)*8 + (lane&7)) * AT_ROWB + ((lane>>3)&1)*16);
    const uint32_t boffV = (uint32_t)(((lane&7) + ((lane>>3)&1)*8) * AT_ROWB + ((lane>>4)&1)*16);

    float o[8][4];
    #pragma unroll
    for (int j = 0; j < 8; j++)
        #pragma unroll
        for (int c = 0; c < 4; c++) o[j][c] = 0.f;
    float mi0 = -1e30f, mi1 = -1e30f, li0 = 0.f, li1 = 0.f;

    for (int kt = 0; kt < 10; kt++) {
        const int c0 = kt * 64;
        const int nk = (SEQ - c0 < 64) ? (SEQ - c0) : 64;
        __syncthreads();
        #pragma unroll
        for (int t = 0; t < 2; t++) {
            int idx = t*256 + tid;
            int r = idx >> 3, c8 = (idx & 7) * 8;
            uint4 kh = z, kl = z, vh = z, vl = z;
            if (r < nk) {
                size_t g = base + (size_t)(c0 + r)*HDIM + c8;
                kh = *(const uint4*)(g_Kh + g); kl = *(const uint4*)(g_Kl + g);
                vh = *(const uint4*)(g_Vh + g); vl = *(const uint4*)(g_Vl + g);
            }
            uint32_t so = (uint32_t)(r*AT_ROWB + c8*2);
            *(uint4*)(smc + AKH + so) = kh; *(uint4*)(smc + AKL + so) = kl;
            *(uint4*)(smc + AVH + so) = vh; *(uint4*)(smc + AVL + so) = vl;
        }
        __syncthreads();

        float sc[8][4];
        #pragma unroll
        for (int j = 0; j < 8; j++)
            #pragma unroll
            for (int c = 0; c < 4; c++) sc[j][c] = 0.f;
        #pragma unroll
        for (int t = 0; t < 4; t++) {
            uint32_t kf[4][4], aq[4];
            #pragma unroll
            for (int j2 = 0; j2 < 4; j2++)
                ldsm4(kf[j2], su + AKH + boffK + (uint32_t)(j2*16*AT_ROWB) + t*32);
            ldsm4(aq, su + AQH + aoff + t*32);
            #pragma unroll
            for (int j2 = 0; j2 < 4; j2++) {
                mma_bf16(sc[2*j2],   aq, &kf[j2][0]);
                mma_bf16(sc[2*j2+1], aq, &kf[j2][2]);
            }
            ldsm4(aq, su + AQL + aoff + t*32);
            #pragma unroll
            for (int j2 = 0; j2 < 4; j2++) {
                mma_bf16(sc[2*j2],   aq, &kf[j2][0]);
                mma_bf16(sc[2*j2+1], aq, &kf[j2][2]);
            }
            #pragma unroll
            for (int j2 = 0; j2 < 4; j2++)
                ldsm4(kf[j2], su + AKL + boffK + (uint32_t)(j2*16*AT_ROWB) + t*32);
            ldsm4(aq, su + AQH + aoff + t*32);
            #pragma unroll
            for (int j2 = 0; j2 < 4; j2++) {
                mma_bf16(sc[2*j2],   aq, &kf[j2][0]);
                mma_bf16(sc[2*j2+1], aq, &kf[j2][2]);
            }
        }

        if (nk < 64) {
            #pragma unroll
            for (int j = 0; j < 8; j++) {
                int col = 8*j + (lane & 3)*2;
                if (col   >= nk) { sc[j][0] = -1e30f; sc[j][2] = -1e30f; }
                if (col+1 >= nk) { sc[j][1] = -1e30f; sc[j][3] = -1e30f; }
            }
        }

        float m0 = -1e30f, m1 = -1e30f;
        #pragma unroll
        for (int j = 0; j < 8; j++) {
            m0 = fmaxf(m0, fmaxf(sc[j][0], sc[j][1]));
            m1 = fmaxf(m1, fmaxf(sc[j][2], sc[j][3]));
        }
        m0 = fmaxf(m0, __shfl_xor_sync(0xffffffffu, m0, 1));
        m0 = fmaxf(m0, __shfl_xor_sync(0xffffffffu, m0, 2));
        m1 = fmaxf(m1, __shfl_xor_sync(0xffffffffu, m1, 1));
        m1 = fmaxf(m1, __shfl_xor_sync(0xffffffffu, m1, 2));
        float mn0 = fmaxf(mi0, m0), mn1 = fmaxf(mi1, m1);
        float cr0 = __expf(mi0 - mn0), cr1 = __expf(mi1 - mn1);
        float rs0 = 0.f, rs1 = 0.f;
        #pragma unroll
        for (int j = 0; j < 8; j++) {
            sc[j][0] = __expf(sc[j][0] - mn0); rs0 += sc[j][0];
            sc[j][1] = __expf(sc[j][1] - mn0); rs0 += sc[j][1];
            sc[j][2] = __expf(sc[j][2] - mn1); rs1 += sc[j][2];
            sc[j][3] = __expf(sc[j][3] - mn1); rs1 += sc[j][3];
        }
        rs0 += __shfl_xor_sync(0xffffffffu, rs0, 1);
        rs0 += __shfl_xor_sync(0xffffffffu, rs0, 2);
        rs1 += __shfl_xor_sync(0xffffffffu, rs1, 1);
        rs1 += __shfl_xor_sync(0xffffffffu, rs1, 2);
        li0 = li0*cr0 + rs0; li1 = li1*cr1 + rs1;
        mi0 = mn0; mi1 = mn1;
        #pragma unroll
        for (int j = 0; j < 8; j++) {
            o[j][0] *= cr0; o[j][1] *= cr0;
            o[j][2] *= cr1; o[j][3] *= cr1;
        }

        #pragma unroll
        for (int tk = 0; tk < 4; tk++) {
            uint32_t ah[4], al[4];
            split2(sc[2*tk][0],   sc[2*tk][1],   ah[0], al[0]);
            split2(sc[2*tk][2],   sc[2*tk][3],   ah[1], al[1]);
            split2(sc[2*tk+1][0], sc[2*tk+1][1], ah[2], al[2]);
            split2(sc[2*tk+1][2], sc[2*tk+1][3], ah[3], al[3]);
            #pragma unroll
            for (int j2 = 0; j2 < 4; j2++) {
                uint32_t vf[4];
                ldsm4t(vf, su + AVH + boffV + (uint32_t)(tk*16*AT_ROWB) + j2*32);
                mma_bf16(o[2*j2],   ah, &vf[0]);
                mma_bf16(o[2*j2+1], ah, &vf[2]);
                mma_bf16(o[2*j2],   al, &vf[0]);
                mma_bf16(o[2*j2+1], al, &vf[2]);
                ldsm4t(vf, su + AVL + boffV + (uint32_t)(tk*16*AT_ROWB) + j2*32);
                mma_bf16(o[2*j2],   ah, &vf[0]);
                mma_bf16(o[2*j2+1], ah, &vf[2]);
            }
        }
    }

    float inv0 = 1.f / li0, inv1 = 1.f / li1;
    const int r0 = q0 + w*16 + (lane >> 2), r1 = r0 + 8;
    #pragma unroll
    for (int j = 0; j < 8; j++) {
        const int col = h*HDIM + 8*j + (lane & 3)*2;
        if (r0 < SEQ) {
            uint32_t hi, lo;
            split2(o[j][0]*inv0, o[j][1]*inv0, hi, lo);
            size_t idx = ((size_t)b*SEQ + r0)*CDIM + col;
            *(uint32_t*)(g_ah + idx) = hi; *(uint32_t*)(g_al + idx) = lo;
        }
        if (r1 < SEQ) {
            uint32_t hi, lo;
            split2(o[j][2]*inv1, o[j][3]*inv1, hi, lo);
            size_t idx = ((size_t)b*SEQ + r1)*CDIM + col;
            *(uint32_t*)(g_ah + idx) = hi; *(uint32_t*)(g_al + idx) = lo;
        }
    }
}

extern "C" void kernel_launch(void* const* d_in, const int* in_sizes, int n_in,
                              void* d_out, int out_size) {
    const float* x     = (const float*)d_in[0];
    const float* Wqkv  = (const float*)d_in[1];
    const float* Wproj = (const float*)d_in[2];
    const float* bproj = (const float*)d_in[3];
    float* out = (float*)d_out;
    (void)in_sizes; (void)n_in; (void)out_size;

    cudaFuncSetAttribute(qkv_mma_kernel,  cudaFuncAttributeMaxDynamicSharedMemorySize, GEMM_SMEM);
    cudaFuncSetAttribute(proj_mma_kernel, cudaFuncAttributeMaxDynamicSharedMemorySize, GEMM_SMEM);
    cudaFuncSetAttribute(attn_kernel_fn,  cudaFuncAttributeMaxDynamicSharedMemorySize, ATTN_SMEM);

    cvt_x_kernel <<<13848, 256>>>(x);
    cvt_wq_kernel<<<1728,  256>>>(Wqkv);
    cvt_wp_kernel<<<576,   256>>>(Wproj);
    qkv_mma_kernel<<<dim3(18, 145), 512, GEMM_SMEM>>>();
    attn_kernel_fn<<<dim3(5, HEADS, BATCH), 256, ATTN_SMEM>>>();
    proj_mma_kernel<<<dim3(6, 145), 512, GEMM_SMEM>>>(out, bproj);
}

// round 16
// speedup vs baseline: 1.0209x; 1.0098x over previous
#include <cuda_runtime.h>
#include <cuda_bf16.h>
#include <cstdint>

#define BATCH 32
#define SEQ   577
#define HEADS 12
#define HDIM  64
#define CDIM  768
#define MROWS (BATCH*SEQ)
#define QKVN  2304

__device__ __nv_bfloat16 g_Qh[(size_t)BATCH*HEADS*SEQ*HDIM], g_Ql[(size_t)BATCH*HEADS*SEQ*HDIM];
__device__ __nv_bfloat16 g_Kh[(size_t)BATCH*HEADS*SEQ*HDIM], g_Kl[(size_t)BATCH*HEADS*SEQ*HDIM];
__device__ __nv_bfloat16 g_Vh[(size_t)BATCH*HEADS*SEQ*HDIM], g_Vl[(size_t)BATCH*HEADS*SEQ*HDIM];
__device__ __nv_bfloat16 g_xh[(size_t)MROWS*CDIM], g_xl[(size_t)MROWS*CDIM];
__device__ __nv_bfloat16 g_wqh[(size_t)QKVN*CDIM], g_wql[(size_t)QKVN*CDIM];
__device__ __nv_bfloat16 g_wph[(size_t)CDIM*CDIM], g_wpl[(size_t)CDIM*CDIM];
__device__ __nv_bfloat16 g_ah[(size_t)MROWS*CDIM], g_al[(size_t)MROWS*CDIM];

// ---------------- helpers ----------------
__device__ __forceinline__ void ldsm4(uint32_t* r, uint32_t addr) {
    asm volatile("ldmatrix.sync.aligned.m8n8.x4.shared.b16 {%0,%1,%2,%3}, [%4];"
        : "=r"(r[0]), "=r"(r[1]), "=r"(r[2]), "=r"(r[3]) : "r"(addr));
}
__device__ __forceinline__ void ldsm4t(uint32_t* r, uint32_t addr) {
    asm volatile("ldmatrix.sync.aligned.m8n8.x4.trans.shared.b16 {%0,%1,%2,%3}, [%4];"
        : "=r"(r[0]), "=r"(r[1]), "=r"(r[2]), "=r"(r[3]) : "r"(addr));
}
__device__ __forceinline__ void mma_bf16(float* c, const uint32_t* a, const uint32_t* b) {
    asm volatile("mma.sync.aligned.m16n8k16.row.col.f32.bf16.bf16.f32 "
        "{%0,%1,%2,%3}, {%4,%5,%6,%7}, {%8,%9}, {%0,%1,%2,%3};"
        : "+f"(c[0]), "+f"(c[1]), "+f"(c[2]), "+f"(c[3])
        : "r"(a[0]), "r"(a[1]), "r"(a[2]), "r"(a[3]), "r"(b[0]), "r"(b[1]));
}
__device__ __forceinline__ void split2(float a, float b, uint32_t& hi, uint32_t& lo) {
    __nv_bfloat16 ha = __float2bfloat16_rn(a);
    __nv_bfloat16 hb = __float2bfloat16_rn(b);
    __nv_bfloat162 h; h.x = ha; h.y = hb;
    hi = *(uint32_t*)&h;
    __nv_bfloat16 la = __float2bfloat16_rn(a - __bfloat162float(ha));
    __nv_bfloat16 lb = __float2bfloat16_rn(b - __bfloat162float(hb));
    __nv_bfloat162 l; l.x = la; l.y = lb;
    lo = *(uint32_t*)&l;
}
__device__ __forceinline__ void cpa16(uint32_t dst, const void* src, int sz) {
    asm volatile("cp.async.cg.shared.global [%0], [%1], 16, %2;" :: "r"(dst), "l"(src), "r"(sz));
}
__device__ __forceinline__ void cpa_commit() { asm volatile("cp.async.commit_group;"); }
__device__ __forceinline__ void cpa_wait1()  { asm volatile("cp.async.wait_group 1;"); }

// ---------------- fp32 -> bf16 hi/lo split kernels ----------------
__device__ __forceinline__ void cvt_body(const float* __restrict__ s,
                                         __nv_bfloat16* __restrict__ hi,
                                         __nv_bfloat16* __restrict__ lo) {
    size_t i = ((size_t)blockIdx.x * 256 + threadIdx.x) * 4;
    float4 v = *(const float4*)(s + i);
    uint32_t h0, l0, h1, l1;
    split2(v.x, v.y, h0, l0);
    split2(v.z, v.w, h1, l1);
    *(uint32_t*)(hi + i) = h0; *(uint32_t*)(hi + i + 2) = h1;
    *(uint32_t*)(lo + i) = l0; *(uint32_t*)(lo + i + 2) = l1;
}
__global__ __launch_bounds__(256) void cvt_x_kernel(const float* __restrict__ s)  { cvt_body(s, g_xh, g_xl); }
__global__ __launch_bounds__(256) void cvt_wq_kernel(const float* __restrict__ s) { cvt_body(s, g_wqh, g_wql); }
__global__ __launch_bounds__(256) void cvt_wp_kernel(const float* __restrict__ s) { cvt_body(s, g_wph, g_wpl); }

// ---------------- HMMA GEMM core: 128x128 tile, BK=32, 16 warps (32x32 each)
// 3-stage cp.async, ONE sync per k-tile. A and B each ONE array of 128B rows:
// [hi 64B | lo 64B], 16B chunks XOR-swizzled by (row&7) -> ldsm conflict-free.
// SPLIT ACCUMULATORS: accA gets ah*bh + al*bh (2-chain), accB gets ah*bl (1-chain).
#define OA 0
#define OB 16384
#define STAGE_BYTES 32768
#define GEMM_SMEM (3*STAGE_BYTES)
#define NKT 24

__device__ __forceinline__ void mma_core(const __nv_bfloat16* __restrict__ Ah,
                                         const __nv_bfloat16* __restrict__ Al,
                                         const __nv_bfloat16* __restrict__ Bh,
                                         const __nv_bfloat16* __restrict__ Bl,
                                         int mBase, int nBase,
                                         float accA[2][4][4], float accB[2][4][4]) {
    extern __shared__ char smc[];
    const uint32_t su = (uint32_t)__cvta_generic_to_shared(smc);
    const int tid = threadIdx.x;
    const int lane = tid & 31, w = tid >> 5;
    const int wm = w & 3, wn = w >> 2;
    const int lrow = tid >> 2, lch = tid & 3;
    const int aSz = ((mBase + lrow) < MROWS) ? 16 : 0;
    const __nv_bfloat16* pAh = Ah + (size_t)(mBase + lrow) * CDIM + lch * 8;
    const __nv_bfloat16* pAl = Al + (size_t)(mBase + lrow) * CDIM + lch * 8;
    const __nv_bfloat16* pBh = Bh + (size_t)(nBase + lrow) * CDIM + lch * 8;
    const __nv_bfloat16* pBl = Bl + (size_t)(nBase + lrow) * CDIM + lch * 8;
    const uint32_t stHi = (uint32_t)lrow * 128 + (uint32_t)((lch ^ (lrow & 7)) << 4);
    const uint32_t stLo = stHi ^ 64;
    const uint32_t lsw  = (uint32_t)(lane & 7);
    const uint32_t aRow = (uint32_t)(wm * 32 + (lane & 15));
    const uint32_t aKh  = (uint32_t)(lane >> 4);
    const uint32_t bRow = (uint32_t)(wn * 32 + ((lane >> 4) << 3) + (lane & 7));
    const uint32_t bKh  = (uint32_t)((lane >> 3) & 1);

    auto issue = [&](int t, int slot) {
        const uint32_t sb = su + (uint32_t)slot * STAGE_BYTES;
        const int k0 = t * 32;
        cpa16(sb + OA + stHi, pAh + k0, aSz);
        cpa16(sb + OA + stLo, pAl + k0, aSz);
        cpa16(sb + OB + stHi, pBh + k0, 16);
        cpa16(sb + OB + stLo, pBl + k0, 16);
        cpa_commit();
    };

    issue(0, 0);
    issue(1, 1);

    int slotC = 0, slotW = 2;
    for (int t = 0; t < NKT; t++) {
        cpa_wait1();
        __syncthreads();
        if (t + 2 < NKT) issue(t + 2, slotW);
        else             cpa_commit();
        const uint32_t sb = su + (uint32_t)slotC * STAGE_BYTES;
        #pragma unroll
        for (int ks = 0; ks < 2; ks++) {
            const uint32_t aOffH = (((uint32_t)(2*ks) + aKh) ^ lsw) << 4;
            const uint32_t bOffH = (((uint32_t)(2*ks) + bKh) ^ lsw) << 4;
            uint32_t afh[2][4], afl[2][4], bhf[4][2], blf[4][2];
            // all frag loads up front (issue stream covers latency)
            #pragma unroll
            for (int i = 0; i < 2; i++)
                ldsm4(afh[i], sb + OA + (aRow + i*16)*128 + aOffH);
            #pragma unroll
            for (int j2 = 0; j2 < 2; j2++) {
                uint32_t r[4];
                ldsm4(r, sb + OB + (bRow + j2*16)*128 + bOffH);
                bhf[2*j2][0]=r[0]; bhf[2*j2][1]=r[1]; bhf[2*j2+1][0]=r[2]; bhf[2*j2+1][1]=r[3];
                ldsm4(r, sb + OB + (bRow + j2*16)*128 + (bOffH ^ 64));
                blf[2*j2][0]=r[0]; blf[2*j2][1]=r[1]; blf[2*j2+1][0]=r[2]; blf[2*j2+1][1]=r[3];
            }
            #pragma unroll
            for (int i = 0; i < 2; i++)
                ldsm4(afl[i], sb + OA + (aRow + i*16)*128 + (aOffH ^ 64));
            // accA: chain step 1 of 2
            #pragma unroll
            for (int i = 0; i < 2; i++)
                #pragma unroll
                for (int j = 0; j < 4; j++)
                    mma_bf16(accA[i][j], afh[i], bhf[j]);
            // accB: independent bank (8 issues between accA's chain steps)
            #pragma unroll
            for (int i = 0; i < 2; i++)
                #pragma unroll
                for (int j = 0; j < 4; j++)
                    mma_bf16(accB[i][j], afh[i], blf[j]);
            // accA: chain step 2 of 2
            #pragma unroll
            for (int i = 0; i < 2; i++)
                #pragma unroll
                for (int j = 0; j < 4; j++)
                    mma_bf16(accA[i][j], afl[i], bhf[j]);
        }
        slotC = (slotC == 2) ? 0 : slotC + 1;
        slotW = (slotW == 2) ? 0 : slotW + 1;
    }
}

// qkv: epilogue sums acc banks, emits bf16 hi/lo Q/K/V (Q pre-scaled by 1/8)
__global__ __launch_bounds__(512, 1) void qkv_mma_kernel() {
    const int mBase = blockIdx.y * 128, nBase = blockIdx.x * 128;
    float accA[2][4][4], accB[2][4][4];
    #pragma unroll
    for (int i = 0; i < 2; i++)
        #pragma unroll
        for (int j = 0; j < 4; j++)
            #pragma unroll
            for (int c = 0; c < 4; c++) { accA[i][j][c] = 0.f; accB[i][j][c] = 0.f; }
    mma_core(g_xh, g_xl, g_wqh, g_wql, mBase, nBase, accA, accB);

    const int lane = threadIdx.x & 31, w = threadIdx.x >> 5;
    const int wm = w & 3, wn = w >> 2;
    const int part = nBase / CDIM;
    __nv_bfloat16* dsth = (part == 0) ? g_Qh : (part == 1) ? g_Kh : g_Vh;
    __nv_bfloat16* dstl = (part == 0) ? g_Ql : (part == 1) ? g_Kl : g_Vl;
    const float scale = (part == 0) ? 0.125f : 1.0f;
    const int nOff = nBase - part * CDIM;
    #pragma unroll
    for (int i = 0; i < 2; i++) {
        const int m0 = mBase + wm*32 + i*16 + (lane >> 2);
        #pragma unroll
        for (int j = 0; j < 4; j++) {
            const int ncol = nOff + wn*32 + j*8 + (lane & 3)*2;
            const int hd = ncol >> 6, d0 = ncol & 63;
            float f[4];
            #pragma unroll
            for (int c = 0; c < 4; c++) f[c] = (accA[i][j][c] + accB[i][j][c]) * scale;
            if (m0 < MROWS) {
                int b = m0 / SEQ, q = m0 - b * SEQ;
                size_t idx = ((size_t)(b*HEADS + hd)*SEQ + q)*HDIM + d0;
                uint32_t hi, lo;
                split2(f[0], f[1], hi, lo);
                *(uint32_t*)(dsth + idx) = hi; *(uint32_t*)(dstl + idx) = lo;
            }
            const int m1 = m0 + 8;
            if (m1 < MROWS) {
                int b = m1 / SEQ, q = m1 - b * SEQ;
                size_t idx = ((size_t)(b*HEADS + hd)*SEQ + q)*HDIM + d0;
                uint32_t hi, lo;
                split2(f[2], f[3], hi, lo);
                *(uint32_t*)(dsth + idx) = hi; *(uint32_t*)(dstl + idx) = lo;
            }
        }
    }
}

__global__ __launch_bounds__(512, 1) void proj_mma_kernel(float* __restrict__ out,
                                                          const float* __restrict__ bias) {
    const int mBase = blockIdx.y * 128, nBase = blockIdx.x * 128;
    float accA[2][4][4], accB[2][4][4];
    #pragma unroll
    for (int i = 0; i < 2; i++)
        #pragma unroll
        for (int j = 0; j < 4; j++)
            #pragma unroll
            for (int c = 0; c < 4; c++) { accA[i][j][c] = 0.f; accB[i][j][c] = 0.f; }
    mma_core(g_ah, g_al, g_wph, g_wpl, mBase, nBase, accA, accB);

    const int lane = threadIdx.x & 31, w = threadIdx.x >> 5;
    const int wm = w & 3, wn = w >> 2;
    #pragma unroll
    for (int i = 0; i < 2; i++) {
        const int m0 = mBase + wm*32 + i*16 + (lane >> 2);
        #pragma unroll
        for (int j = 0; j < 4; j++) {
            const int ncol = nBase + wn*32 + j*8 + (lane & 3)*2;
            const float2 bv = *(const float2*)(bias + ncol);
            if (m0 < MROWS)
                *(float2*)(out + (size_t)m0*CDIM + ncol) =
                    make_float2(accA[i][j][0] + accB[i][j][0] + bv.x,
                                accA[i][j][1] + accB[i][j][1] + bv.y);
            const int m1 = m0 + 8;
            if (m1 < MROWS)
                *(float2*)(out + (size_t)m1*CDIM + ncol) =
                    make_float2(accA[i][j][2] + accB[i][j][2] + bv.x,
                                accA[i][j][3] + accB[i][j][3] + bv.y);
        }
    }
}

// ---------------- HMMA flash attention (unchanged from R8/R13) ----------------
#define AT_ROWB 144
#define AQH 0
#define AQL 18432
#define AKH 36864
#define AKL 46080
#define AVH 55296
#define AVL 64512
#define ATTN_SMEM 73728

__global__ __launch_bounds__(256, 2) void attn_kernel_fn() {
    extern __shared__ char smc[];
    const uint32_t su = (uint32_t)__cvta_generic_to_shared(smc);
    const int tid = threadIdx.x;
    const int lane = tid & 31, w = tid >> 5;
    const int b = blockIdx.z, h = blockIdx.y;
    const int q0 = blockIdx.x * 128;
    const size_t base = (size_t)(b*HEADS + h) * SEQ * HDIM;
    const uint4 z = make_uint4(0, 0, 0, 0);

    #pragma unroll
    for (int t = 0; t < 4; t++) {
        int idx = t*256 + tid;
        int r = idx >> 3, c8 = (idx & 7) * 8;
        uint4 vh = z, vl = z;
        if (q0 + r < SEQ) {
            size_t g = base + (size_t)(q0 + r)*HDIM + c8;
            vh = *(const uint4*)(g_Qh + g);
            vl = *(const uint4*)(g_Ql + g);
        }
        *(uint4*)(smc + AQH + r*AT_ROWB + c8*2) = vh;
        *(uint4*)(smc + AQL + r*AT_ROWB + c8*2) = vl;
    }

    const uint32_t aoff  = (uint32_t)((w*16 + (lane&7) + ((lane>>3)&1)*8) * AT_ROWB + ((lane>>4)&1)*16);
    const uint32_t boffK = (uint32_t)((((lane>>4)&1)*8 + (lane&7)) * AT_ROWB + ((lane>>3)&1)*16);
    const uint32_t boffV = (uint32_t)(((lane&7) + ((lane>>3)&1)*8) * AT_ROWB + ((lane>>4)&1)*16);

    float o[8][4];
    #pragma unroll
    for (int j = 0; j < 8; j++)
        #pragma unroll
        for (int c = 0; c < 4; c++) o[j][c] = 0.f;
    float mi0 = -1e30f, mi1 = -1e30f, li0 = 0.f, li1 = 0.f;

    for (int kt = 0; kt < 10; kt++) {
        const int c0 = kt * 64;
        const int nk = (SEQ - c0 < 64) ? (SEQ - c0) : 64;
        __syncthreads();
        #pragma unroll
        for (int t = 0; t < 2; t++) {
            int idx = t*256 + tid;
            int r = idx >> 3, c8 = (idx & 7) * 8;
            uint4 kh = z, kl = z, vh = z, vl = z;
            if (r < nk) {
                size_t g = base + (size_t)(c0 + r)*HDIM + c8;
                kh = *(const uint4*)(g_Kh + g); kl = *(const uint4*)(g_Kl + g);
                vh = *(const uint4*)(g_Vh + g); vl = *(const uint4*)(g_Vl + g);
            }
            uint32_t so = (uint32_t)(r*AT_ROWB + c8*2);
            *(uint4*)(smc + AKH + so) = kh; *(uint4*)(smc + AKL + so) = kl;
            *(uint4*)(smc + AVH + so) = vh; *(uint4*)(smc + AVL + so) = vl;
        }
        __syncthreads();

        float sc[8][4];
        #pragma unroll
        for (int j = 0; j < 8; j++)
            #pragma unroll
            for (int c = 0; c < 4; c++) sc[j][c] = 0.f;
        #pragma unroll
        for (int t = 0; t < 4; t++) {
            uint32_t kf[4][4], aq[4];
            #pragma unroll
            for (int j2 = 0; j2 < 4; j2++)
                ldsm4(kf[j2], su + AKH + boffK + (uint32_t)(j2*16*AT_ROWB) + t*32);
            ldsm4(aq, su + AQH + aoff + t*32);
            #pragma unroll
            for (int j2 = 0; j2 < 4; j2++) {
                mma_bf16(sc[2*j2],   aq, &kf[j2][0]);
                mma_bf16(sc[2*j2+1], aq, &kf[j2][2]);
            }
            ldsm4(aq, su + AQL + aoff + t*32);
            #pragma unroll
            for (int j2 = 0; j2 < 4; j2++) {
                mma_bf16(sc[2*j2],   aq, &kf[j2][0]);
                mma_bf16(sc[2*j2+1], aq, &kf[j2][2]);
            }
            #pragma unroll
            for (int j2 = 0; j2 < 4; j2++)
                ldsm4(kf[j2], su + AKL + boffK + (uint32_t)(j2*16*AT_ROWB) + t*32);
            ldsm4(aq, su + AQH + aoff + t*32);
            #pragma unroll
            for (int j2 = 0; j2 < 4; j2++) {
                mma_bf16(sc[2*j2],   aq, &kf[j2][0]);
                mma_bf16(sc[2*j2+1], aq, &kf[j2][2]);
            }
        }

        if (nk < 64) {
            #pragma unroll
            for (int j = 0; j < 8; j++) {
                int col = 8*j + (lane & 3)*2;
                if (col   >= nk) { sc[j][0] = -1e30f; sc[j][2] = -1e30f; }
                if (col+1 >= nk) { sc[j][1] = -1e30f; sc[j][3] = -1e30f; }
            }
        }

        float m0 = -1e30f, m1 = -1e30f;
        #pragma unroll
        for (int j = 0; j < 8; j++) {
            m0 = fmaxf(m0, fmaxf(sc[j][0], sc[j][1]));
            m1 = fmaxf(m1, fmaxf(sc[j][2], sc[j][3]));
        }
        m0 = fmaxf(m0, __shfl_xor_sync(0xffffffffu, m0, 1));
        m0 = fmaxf(m0, __shfl_xor_sync(0xffffffffu, m0, 2));
        m1 = fmaxf(m1, __shfl_xor_sync(0xffffffffu, m1, 1));
        m1 = fmaxf(m1, __shfl_xor_sync(0xffffffffu, m1, 2));
        float mn0 = fmaxf(mi0, m0), mn1 = fmaxf(mi1, m1);
        float cr0 = __expf(mi0 - mn0), cr1 = __expf(mi1 - mn1);
        float rs0 = 0.f, rs1 = 0.f;
        #pragma unroll
        for (int j = 0; j < 8; j++) {
            sc[j][0] = __expf(sc[j][0] - mn0); rs0 += sc[j][0];
            sc[j][1] = __expf(sc[j][1] - mn0); rs0 += sc[j][1];
            sc[j][2] = __expf(sc[j][2] - mn1); rs1 += sc[j][2];
            sc[j][3] = __expf(sc[j][3] - mn1); rs1 += sc[j][3];
        }
        rs0 += __shfl_xor_sync(0xffffffffu, rs0, 1);
        rs0 += __shfl_xor_sync(0xffffffffu, rs0, 2);
        rs1 += __shfl_xor_sync(0xffffffffu, rs1, 1);
        rs1 += __shfl_xor_sync(0xffffffffu, rs1, 2);
        li0 = li0*cr0 + rs0; li1 = li1*cr1 + rs1;
        mi0 = mn0; mi1 = mn1;
        #pragma unroll
        for (int j = 0; j < 8; j++) {
            o[j][0] *= cr0; o[j][1] *= cr0;
            o[j][2] *= cr1; o[j][3] *= cr1;
        }

        #pragma unroll
        for (int tk = 0; tk < 4; tk++) {
            uint32_t ah[4], al[4];
            split2(sc[2*tk][0],   sc[2*tk][1],   ah[0], al[0]);
            split2(sc[2*tk][2],   sc[2*tk][3],   ah[1], al[1]);
            split2(sc[2*tk+1][0], sc[2*tk+1][1], ah[2], al[2]);
            split2(sc[2*tk+1][2], sc[2*tk+1][3], ah[3], al[3]);
            #pragma unroll
            for (int j2 = 0; j2 < 4; j2++) {
                uint32_t vf[4];
                ldsm4t(vf, su + AVH + boffV + (uint32_t)(tk*16*AT_ROWB) + j2*32);
                mma_bf16(o[2*j2],   ah, &vf[0]);
                mma_bf16(o[2*j2+1], ah, &vf[2]);
                mma_bf16(o[2*j2],   al, &vf[0]);
                mma_bf16(o[2*j2+1], al, &vf[2]);
                ldsm4t(vf, su + AVL + boffV + (uint32_t)(tk*16*AT_ROWB) + j2*32);
                mma_bf16(o[2*j2],   ah, &vf[0]);
                mma_bf16(o[2*j2+1], ah, &vf[2]);
            }
        }
    }

    float inv0 = 1.f / li0, inv1 = 1.f / li1;
    const int r0 = q0 + w*16 + (lane >> 2), r1 = r0 + 8;
    #pragma unroll
    for (int j = 0; j < 8; j++) {
        const int col = h*HDIM + 8*j + (lane & 3)*2;
        if (r0 < SEQ) {
            uint32_t hi, lo;
            split2(o[j][0]*inv0, o[j][1]*inv0, hi, lo);
            size_t idx = ((size_t)b*SEQ + r0)*CDIM + col;
            *(uint32_t*)(g_ah + idx) = hi; *(uint32_t*)(g_al + idx) = lo;
        }
        if (r1 < SEQ) {
            uint32_t hi, lo;
            split2(o[j][2]*inv1, o[j][3]*inv1, hi, lo);
            size_t idx = ((size_t)b*SEQ + r1)*CDIM + col;
            *(uint32_t*)(g_ah + idx) = hi; *(uint32_t*)(g_al + idx) = lo;
        }
    }
}

extern "C" void kernel_launch(void* const* d_in, const int* in_sizes, int n_in,
                              void* d_out, int out_size) {
    const float* x     = (const float*)d_in[0];
    const float* Wqkv  = (const float*)d_in[1];
    const float* Wproj = (const float*)d_in[2];
    const float* bproj = (const float*)d_in[3];
    float* out = (float*)d_out;
    (void)in_sizes; (void)n_in; (void)out_size;

    cudaFuncSetAttribute(qkv_mma_kernel,  cudaFuncAttributeMaxDynamicSharedMemorySize, GEMM_SMEM);
    cudaFuncSetAttribute(proj_mma_kernel, cudaFuncAttributeMaxDynamicSharedMemorySize, GEMM_SMEM);
    cudaFuncSetAttribute(attn_kernel_fn,  cudaFuncAttributeMaxDynamicSharedMemorySize, ATTN_SMEM);

    cvt_x_kernel <<<13848, 256>>>(x);
    cvt_wq_kernel<<<1728,  256>>>(Wqkv);
    cvt_wp_kernel<<<576,   256>>>(Wproj);
    qkv_mma_kernel<<<dim3(18, 145), 512, GEMM_SMEM>>>();
    attn_kernel_fn<<<dim3(5, HEADS, BATCH), 256, ATTN_SMEM>>>();
    proj_mma_kernel<<<dim3(6, 145), 512, GEMM_SMEM>>>(out, bproj);
}